// round 15
// baseline (speedup 1.0000x reference)
#include <cuda_runtime.h>

// LensCrack fused: out = clip(x,0,1) with crack pixels overwritten to 0.05.
// x: [16, 3, 1024, 1024] fp32, endpoints: [16, 8, 4] int32 rows (y0,x0,y1,x1)
//
// One kernel. Each block = 4096 floats = 4 rows of one channel of one batch.
// Warp 0 inverts the closed-form Bresenham per (line,row) to get contiguous
// x-ranges; after the bulk clipped copy + __syncthreads (orders intra-block
// global writes), all threads patch the block's crack pixels.

#define CRACK_VAL 0.05f

static constexpr int Bc = 16;
static constexpr int Cc = 3;
static constexpr int Hc = 1024;
static constexpr int Wc = 1024;
static constexpr int Kc = 8;
static constexpr int HW = Hc * Wc;

// Closed-form Bresenham (validated rel_err==0 in R13/R14):
//   dx >= dy: cx(t) = x0 + sx*t,  cy(t) = y0 + sy*max(0, ceil((2*dy*t - dx)/(2*dx)))
//   dy >  dx: symmetric.
// Per-row inversion (x-major, n = sy*(y-y0), 0<=n<=dy):
//   n = 0 :  t in [0, floor(dx/(2dy))]            (dy>0;  [0,dx] if dy==0 and y==y0)
//   n >= 1:  t in ( dx(2n-1)/(2dy), dx(2n+1)/(2dy) ]
//            -> t_lo = floor(dx(2n-1)/(2dy)) + 1, t_hi = min(dx, floor(dx(2n+1)/(2dy)))

__global__ void __launch_bounds__(256) lenscrack_fused(
    const float4* __restrict__ x, float4* __restrict__ out,
    const int* __restrict__ ep)
{
    __shared__ int s_ent[32];   // packed (y<<20 | xa<<10 | xb)
    __shared__ int s_cnt;

    const int bid = blockIdx.x;
    const int tid = threadIdx.x;
    const int b   = bid / (Cc * 256);          // batch
    const int y4  = (bid & 255) * 4;           // first of 4 rows this block owns
    const int ci  = bid >> 8;                  // channel-image index = b*3 + c

    const float4* xs = x   + (size_t)bid * 1024;
    float4*       os = out + (size_t)bid * 1024;

    // ---- bulk: front-batched loads (MLP=4), streaming hints ----
    float4 v0 = __ldcs(xs + tid);
    float4 v1 = __ldcs(xs + tid + 256);
    float4 v2 = __ldcs(xs + tid + 512);
    float4 v3 = __ldcs(xs + tid + 768);

    v0.x = __saturatef(v0.x); v0.y = __saturatef(v0.y);
    v0.z = __saturatef(v0.z); v0.w = __saturatef(v0.w);
    v1.x = __saturatef(v1.x); v1.y = __saturatef(v1.y);
    v1.z = __saturatef(v1.z); v1.w = __saturatef(v1.w);
    v2.x = __saturatef(v2.x); v2.y = __saturatef(v2.y);
    v2.z = __saturatef(v2.z); v2.w = __saturatef(v2.w);
    v3.x = __saturatef(v3.x); v3.y = __saturatef(v3.y);
    v3.z = __saturatef(v3.z); v3.w = __saturatef(v3.w);

    __stcs(os + tid,       v0);
    __stcs(os + tid + 256, v1);
    __stcs(os + tid + 512, v2);
    __stcs(os + tid + 768, v3);

    // ---- warp 0: per-(line,row) range inversion ----
    if (tid < 32) {
        const int line = b * Kc + (tid >> 2);  // 8 lines of this batch
        const int y    = y4 + (tid & 3);       // one of the block's 4 rows

        const int4 e = __ldg((const int4*)(ep + line * 4)); // y0,x0,y1,x1
        const int y0 = e.x, x0 = e.y, y1 = e.z, x1 = e.w;

        const int dx = abs(x1 - x0);
        const int dy = abs(y1 - y0);
        const int sx = (x0 < x1) ? 1 : -1;
        const int sy = (y0 < y1) ? 1 : -1;

        int xa = 1, xb = 0;                    // empty by default
        if (dx >= dy) {
            const int n = sy * (y - y0);
            if (n >= 0 && n <= dy) {
                int t_lo, t_hi;
                if (dy == 0) {                 // horizontal (or point): y == y0 here
                    t_lo = 0; t_hi = dx;
                } else if (n == 0) {
                    t_lo = 0; t_hi = dx / (2 * dy);
                } else {
                    t_lo = (dx * (2 * n - 1)) / (2 * dy) + 1;
                    t_hi = min(dx, (dx * (2 * n + 1)) / (2 * dy));
                }
                if (sx > 0) { xa = x0 + t_lo; xb = x0 + t_hi; }
                else        { xa = x0 - t_hi; xb = x0 - t_lo; }
                xa = max(xa, 0); xb = min(xb, Wc - 1);
            }
        } else {                               // y-major: single pixel on this row
            const int t = sy * (y - y0);
            if (t >= 0 && t <= dy) {
                const int num = 2 * dx * t - dy;
                const int m = (num <= 0) ? 0 : (num + 2 * dy - 1) / (2 * dy);
                const int cx = x0 + sx * m;
                if ((unsigned)cx < (unsigned)Wc) { xa = cx; xb = cx; }
            }
        }

        const unsigned msk = __ballot_sync(0xffffffffu, xa <= xb);
        if (xa <= xb) {
            const int pos = __popc(msk & ((1u << tid) - 1u));
            s_ent[pos] = (y << 20) | (xa << 10) | xb;
        }
        if (tid == 0) s_cnt = __popc(msk);
    }

    __syncthreads();   // orders bulk STG before patch STG (intra-block)

    // ---- patch: cooperative overwrite of crack pixels ----
    const int cnt = s_cnt;
    float* oc = (float*)out + (size_t)ci * HW;   // this channel-image base
    for (int eidx = 0; eidx < cnt; ++eidx) {
        const int p  = s_ent[eidx];
        const int y  = p >> 20;
        const int xa = (p >> 10) & 1023;
        const int xb = p & 1023;
        float* row = oc + y * Wc;
        for (int j = xa + tid; j <= xb; j += 256)
            row[j] = CRACK_VAL;
    }
}

// ---------------------------------------------------------------------------
extern "C" void kernel_launch(void* const* d_in, const int* in_sizes, int n_in,
                              void* d_out, int out_size)
{
    const float* x  = (const float*)d_in[0];   // 16*3*1024*1024 fp32
    const int*   ep = (const int*)d_in[1];     // 16*8*4 int32
    float* out = (float*)d_out;

    const int blocks = Bc * Cc * 256;          // 12288 blocks x 4096 floats

    lenscrack_fused<<<blocks, 256>>>((const float4*)x, (float4*)out, ep);
}

// round 16
// speedup vs baseline: 1.0010x; 1.0010x over previous
#include <cuda_runtime.h>

// LensCrack fused: out = clip(x,0,1) with crack pixels overwritten to 0.05.
// x: [16, 3, 1024, 1024] fp32, endpoints: [16, 8, 4] int32 rows (y0,x0,y1,x1)
//
// One kernel. Each block = 4096 floats = 4 rows of one channel of one batch.
// Warp 0's lanes each own one (line,row) pair (8 lines x 4 rows) and invert
// the closed-form Bresenham to a contiguous x-range held in registers.
// After the bulk clipped copy + __syncthreads (orders intra-block global
// writes), ONLY warp 0 patches the block's crack pixels (ballot + shfl
// broadcast, 32 lanes striding each range). Warps 1-7 exit at the barrier.

#define CRACK_VAL 0.05f

static constexpr int Bc = 16;
static constexpr int Cc = 3;
static constexpr int Hc = 1024;
static constexpr int Wc = 1024;
static constexpr int Kc = 8;
static constexpr int HW = Hc * Wc;

// Closed-form Bresenham (validated rel_err==0 in R13/R14/R15):
//   dx >= dy: cx(t) = x0 + sx*t,  cy(t) = y0 + sy*max(0, ceil((2*dy*t - dx)/(2*dx)))
//   dy >  dx: symmetric.
// Per-row inversion (x-major, n = sy*(y-y0), 0<=n<=dy):
//   n = 0 :  t in [0, floor(dx/(2dy))]         (dy>0;  [0,dx] if dy==0, y==y0)
//   n >= 1:  t_lo = floor(dx(2n-1)/(2dy)) + 1, t_hi = min(dx, floor(dx(2n+1)/(2dy)))

__global__ void __launch_bounds__(256) lenscrack_fused(
    const float4* __restrict__ x, float4* __restrict__ out,
    const int* __restrict__ ep)
{
    const int bid = blockIdx.x;
    const int tid = threadIdx.x;
    const int b   = bid / (Cc * 256);          // batch
    const int y4  = (bid & 255) * 4;           // first of the 4 rows this block owns
    const int ci  = bid >> 8;                  // channel-image index = b*3 + c

    const float4* xs = x   + (size_t)bid * 1024;
    float4*       os = out + (size_t)bid * 1024;

    // ---- bulk: front-batched loads (MLP=4), streaming hints ----
    float4 v0 = __ldcs(xs + tid);
    float4 v1 = __ldcs(xs + tid + 256);
    float4 v2 = __ldcs(xs + tid + 512);
    float4 v3 = __ldcs(xs + tid + 768);

    // ---- warp 0: per-(line,row) range inversion, registers only ----
    // (independent of the loads above; overlaps their latency)
    int ry = 0, rxa = 1, rxb = 0;              // empty by default
    if (tid < 32) {
        const int line = b * Kc + (tid >> 2);  // this batch's 8 lines
        const int y    = y4 + (tid & 3);       // one of the block's 4 rows
        ry = y;

        const int4 e = __ldg((const int4*)(ep + line * 4)); // y0,x0,y1,x1
        const int y0 = e.x, x0 = e.y, y1 = e.z, x1 = e.w;

        const int dx = abs(x1 - x0);
        const int dy = abs(y1 - y0);
        const int sx = (x0 < x1) ? 1 : -1;
        const int sy = (y0 < y1) ? 1 : -1;

        if (dx >= dy) {
            const int n = sy * (y - y0);
            if (n >= 0 && n <= dy) {
                int t_lo, t_hi;
                if (dy == 0) {                 // horizontal/point: y == y0 here
                    t_lo = 0; t_hi = dx;
                } else if (n == 0) {
                    t_lo = 0; t_hi = dx / (2 * dy);
                } else {
                    t_lo = (dx * (2 * n - 1)) / (2 * dy) + 1;
                    t_hi = min(dx, (dx * (2 * n + 1)) / (2 * dy));
                }
                if (sx > 0) { rxa = x0 + t_lo; rxb = x0 + t_hi; }
                else        { rxa = x0 - t_hi; rxb = x0 - t_lo; }
                rxa = max(rxa, 0); rxb = min(rxb, Wc - 1);
            }
        } else {                               // y-major: single pixel on this row
            const int t = sy * (y - y0);
            if (t >= 0 && t <= dy) {
                const int num = 2 * dx * t - dy;
                const int m = (num <= 0) ? 0 : (num + 2 * dy - 1) / (2 * dy);
                const int cx = x0 + sx * m;
                if ((unsigned)cx < (unsigned)Wc) { rxa = cx; rxb = cx; }
            }
        }
    }

    // ---- bulk: saturate + streaming stores ----
    v0.x = __saturatef(v0.x); v0.y = __saturatef(v0.y);
    v0.z = __saturatef(v0.z); v0.w = __saturatef(v0.w);
    v1.x = __saturatef(v1.x); v1.y = __saturatef(v1.y);
    v1.z = __saturatef(v1.z); v1.w = __saturatef(v1.w);
    v2.x = __saturatef(v2.x); v2.y = __saturatef(v2.y);
    v2.z = __saturatef(v2.z); v2.w = __saturatef(v2.w);
    v3.x = __saturatef(v3.x); v3.y = __saturatef(v3.y);
    v3.z = __saturatef(v3.z); v3.w = __saturatef(v3.w);

    __stcs(os + tid,       v0);
    __stcs(os + tid + 256, v1);
    __stcs(os + tid + 512, v2);
    __stcs(os + tid + 768, v3);

    __syncthreads();   // orders bulk STG before patch STG (intra-block)

    // ---- patch: warp 0 only; warps 1-7 exit here ----
    if (tid < 32) {
        unsigned msk = __ballot_sync(0xffffffffu, rxa <= rxb);
        if (msk) {
            float* oc = (float*)out + (size_t)ci * HW;
            do {
                const int src = __ffs(msk) - 1;
                msk &= msk - 1;
                const int y  = __shfl_sync(0xffffffffu, ry,  src);
                const int xa = __shfl_sync(0xffffffffu, rxa, src);
                const int xb = __shfl_sync(0xffffffffu, rxb, src);
                float* row = oc + y * Wc;
                for (int j = xa + tid; j <= xb; j += 32)
                    row[j] = CRACK_VAL;
            } while (msk);
        }
    }
}

// ---------------------------------------------------------------------------
extern "C" void kernel_launch(void* const* d_in, const int* in_sizes, int n_in,
                              void* d_out, int out_size)
{
    const float* x  = (const float*)d_in[0];   // 16*3*1024*1024 fp32
    const int*   ep = (const int*)d_in[1];     // 16*8*4 int32
    float* out = (float*)d_out;

    const int blocks = Bc * Cc * 256;          // 12288 blocks x 4096 floats

    lenscrack_fused<<<blocks, 256>>>((const float4*)x, (float4*)out, ep);
}

// round 17
// speedup vs baseline: 1.0615x; 1.0605x over previous
#include <cuda_runtime.h>

// LensCrack fused: out = clip(x,0,1) with crack pixels = 0.05, single store.
// x: [16, 3, 1024, 1024] fp32, endpoints: [16, 8, 4] int32 rows (y0,x0,y1,x1)
//
// One kernel, 12288 blocks x 512 threads; block = 4096 floats = 4 rows of one
// channel-image. Each thread's two float4s each cover 4 pixels of ONE row
// (v0: row tid>>8, v1: row 2+(tid>>8)). Warp 0 inverts the closed-form
// Bresenham per (line,row) into per-row x-range lists in smem; after a cheap
// early barrier, every thread merges CRACK_VAL into its register lanes and
// stores ONCE. No write-after-write, no second store pass.

#define CRACK_VAL 0.05f

static constexpr int Bc = 16;
static constexpr int Cc = 3;
static constexpr int Hc = 1024;
static constexpr int Wc = 1024;
static constexpr int Kc = 8;
static constexpr int HW = Hc * Wc;

// Closed-form Bresenham (validated rel_err==0 in R13-R16):
//   dx >= dy: cx(t) = x0 + sx*t,  cy(t) = y0 + sy*max(0, ceil((2*dy*t - dx)/(2*dx)))
//   dy >  dx: symmetric.
// Per-row inversion (x-major, n = sy*(y-y0), 0<=n<=dy):
//   n = 0 :  t in [0, floor(dx/(2dy))]         (dy>0;  [0,dx] if dy==0, y==y0)
//   n >= 1:  t_lo = floor(dx(2n-1)/(2dy)) + 1, t_hi = min(dx, floor(dx(2n+1)/(2dy)))

__global__ void __launch_bounds__(512) lenscrack_fused(
    const float4* __restrict__ x, float4* __restrict__ out,
    const int* __restrict__ ep)
{
    __shared__ int s_cnt[4];
    __shared__ int s_rng[4][8];   // packed (xa<<10 | xb), per row

    const int bid = blockIdx.x;
    const int tid = threadIdx.x;
    const int b   = bid / (Cc * 256);          // batch
    const int y4  = (bid & 255) * 4;           // first of the block's 4 rows

    const float4* xs = x   + (size_t)bid * 1024;
    float4*       os = out + (size_t)bid * 1024;

    // ---- bulk loads first: MLP=2 (matches R14's 89%-BW copy body) ----
    float4 v0 = __ldcs(xs + tid);
    float4 v1 = __ldcs(xs + tid + 512);

    // ---- warp 0: per-(line,row) range inversion -> per-row smem lists ----
    if (tid < 32) {
        const int line = b * Kc + (tid >> 2);  // this batch's 8 lines
        const int r    = tid & 3;              // row index within block
        const int y    = y4 + r;

        const int4 e = __ldg((const int4*)(ep + line * 4)); // y0,x0,y1,x1
        const int y0 = e.x, x0 = e.y, y1 = e.z, x1 = e.w;

        const int dx = abs(x1 - x0);
        const int dy = abs(y1 - y0);
        const int sx = (x0 < x1) ? 1 : -1;
        const int sy = (y0 < y1) ? 1 : -1;

        int xa = 1, xb = 0;                    // empty by default
        if (dx >= dy) {
            const int n = sy * (y - y0);
            if (n >= 0 && n <= dy) {
                int t_lo, t_hi;
                if (dy == 0) {                 // horizontal/point: y == y0 here
                    t_lo = 0; t_hi = dx;
                } else if (n == 0) {
                    t_lo = 0; t_hi = dx / (2 * dy);
                } else {
                    t_lo = (dx * (2 * n - 1)) / (2 * dy) + 1;
                    t_hi = min(dx, (dx * (2 * n + 1)) / (2 * dy));
                }
                if (sx > 0) { xa = x0 + t_lo; xb = x0 + t_hi; }
                else        { xa = x0 - t_hi; xb = x0 - t_lo; }
                xa = max(xa, 0); xb = min(xb, Wc - 1);
            }
        } else {                               // y-major: single pixel on this row
            const int t = sy * (y - y0);
            if (t >= 0 && t <= dy) {
                const int num = 2 * dx * t - dy;
                const int m = (num <= 0) ? 0 : (num + 2 * dy - 1) / (2 * dy);
                const int cx = x0 + sx * m;
                if ((unsigned)cx < (unsigned)Wc) { xa = cx; xb = cx; }
            }
        }

        const unsigned msk = __ballot_sync(0xffffffffu, xa <= xb);
        if (xa <= xb) {
            const unsigned rowmask = 0x11111111u << r;   // lanes r, r+4, ..., r+28
            const int pos = __popc(msk & rowmask & ((1u << tid) - 1u));
            s_rng[r][pos] = (xa << 10) | xb;
        }
        if (tid < 4) s_cnt[tid] = __popc(msk & (0x11111111u << tid));
    }

    // Cheap barrier: only warp 0's single ep load gates it, and that latency
    // overlaps the bulk loads already in flight.
    __syncthreads();

    // ---- saturate ----
    v0.x = __saturatef(v0.x); v0.y = __saturatef(v0.y);
    v0.z = __saturatef(v0.z); v0.w = __saturatef(v0.w);
    v1.x = __saturatef(v1.x); v1.y = __saturatef(v1.y);
    v1.z = __saturatef(v1.z); v1.w = __saturatef(v1.w);

    // ---- merge crack ranges into register lanes (CRACK_VAL in [0,1]) ----
    const int r0 = tid >> 8;                   // v0's row (0 or 1); v1's = r0+2
    const int X  = (tid << 2) & 1023;          // x of lane 0

    const int c0 = s_cnt[r0];
    for (int k = 0; k < c0; ++k) {
        const int p  = s_rng[r0][k];
        const int xa = p >> 10, xb = p & 1023;
        if (X + 3 >= xa && X <= xb) {
            if (X     >= xa && X     <= xb) v0.x = CRACK_VAL;
            if (X + 1 >= xa && X + 1 <= xb) v0.y = CRACK_VAL;
            if (X + 2 >= xa && X + 2 <= xb) v0.z = CRACK_VAL;
            if (X + 3 >= xa && X + 3 <= xb) v0.w = CRACK_VAL;
        }
    }
    const int c1 = s_cnt[r0 + 2];
    for (int k = 0; k < c1; ++k) {
        const int p  = s_rng[r0 + 2][k];
        const int xa = p >> 10, xb = p & 1023;
        if (X + 3 >= xa && X <= xb) {
            if (X     >= xa && X     <= xb) v1.x = CRACK_VAL;
            if (X + 1 >= xa && X + 1 <= xb) v1.y = CRACK_VAL;
            if (X + 2 >= xa && X + 2 <= xb) v1.z = CRACK_VAL;
            if (X + 3 >= xa && X + 3 <= xb) v1.w = CRACK_VAL;
        }
    }

    // ---- single streaming store per vector ----
    __stcs(os + tid,       v0);
    __stcs(os + tid + 512, v1);
}

// ---------------------------------------------------------------------------
extern "C" void kernel_launch(void* const* d_in, const int* in_sizes, int n_in,
                              void* d_out, int out_size)
{
    const float* x  = (const float*)d_in[0];   // 16*3*1024*1024 fp32
    const int*   ep = (const int*)d_in[1];     // 16*8*4 int32
    float* out = (float*)d_out;

    const int blocks = Bc * Cc * 256;          // 12288 blocks x 4096 floats

    lenscrack_fused<<<blocks, 512>>>((const float4*)x, (float4*)out, ep);
}